// round 2
// baseline (speedup 1.0000x reference)
#include <cuda_runtime.h>
#include <cuda_bf16.h>

#define DEV __device__ __forceinline__

// ---------------- scratch (no allocations allowed) ----------------
__device__ float g_s1l[32 * 256 * 16];   // stage1 LoTe out  [b,256,16]
__device__ float g_s1c[32 * 1024 * 16];  // stage1 Conv out  [b,1024,16]
__device__ float g_s2[32 * 64 * 32];     // stage2 out       [b,64,32] (lo2|co2)
__device__ float g_s3[32 * 16 * 32];     // stage3 out       [b,16,32] (lo3|co3)

// ---------------- gathers (exact unfold/reshape index math) ----------------
struct GLote1 {  // lx[b,a,p,l], a<48,p<256,l<4 from x[b,3,128,128], window 16
    const float* x;
    DEV float operator()(int b, int a, int p, int l) const {
        int flat = a * 1024 + p * 4 + l;
        int c = flat >> 14; int r = flat & 16383;   // strides 16384,2048,256,16,1
        int hb = r >> 11; r &= 2047;
        int wb = r >> 8;  r &= 255;
        int h = (hb << 4) + (r >> 4);
        int w = (wb << 4) + (r & 15);
        return x[((b * 3 + c) << 14) + (h << 7) + w];
    }
};
struct GConv1 {  // cx[b,a,p,l], a<16,p<1024,l<3, window 4
    const float* x;
    DEV float operator()(int b, int a, int p, int l) const {
        int flat = a * 3072 + p * 3 + l;
        int c = flat >> 14; int r = flat & 16383;   // strides 16384,512,16,4,1
        int hb = r >> 9; r &= 511;
        int wb = r >> 4; r &= 15;
        int h = (hb << 2) + (r >> 2);
        int w = (wb << 2) + (r & 3);
        return x[((b * 3 + c) << 14) + (h << 7) + w];
    }
};
struct GComb {   // comb[b,a,p,l]: a<16,p<64,l<20; l<4 -> ly2, else cy2^T
    const float* ly;  // g_s1l normalized, viewed [b,16,16,16] via ch=d*16+h,o=w
    const float* cy;  // g_s1c normalized, viewed [b,16,32,32]
    DEV float operator()(int b, int a, int p, int l) const {
        if (l < 4) {
            int r = (p << 2) + l;       // c = a; strides within: 128,64,8,1
            int hb = r >> 7; r &= 127;
            int wb = r >> 6; r &= 63;
            int h = (hb << 3) + (r >> 3);
            int w = (wb << 3) + (r & 7);
            return ly[(b * 256 + (a << 4) + h) * 16 + w];
        } else {
            int a2 = l - 4, l2 = a;
            int r = (p << 4) + l2;      // c = a2; strides: 128,16,4,1
            int hb = r >> 7; r &= 127;
            int wb = r >> 4; r &= 15;
            int h = (hb << 2) + (r >> 2);
            int w = (wb << 2) + (r & 3);
            int f3 = (a2 << 10) + (h << 5) + w;     // cy flat c*1024+h*32+w
            return cy[(b * 1024 + (f3 >> 4)) * 16 + (f3 & 15)];
        }
    }
};
struct GConv2 {  // transpose(comb,(0,3,2,1)): (b,a<20,p,l<16) -> comb(b,l,p,a)
    GComb inner;
    DEV float operator()(int b, int a, int p, int l) const { return inner(b, l, p, a); }
};
struct GL3 {     // lx3[b,a,p,l], a<32,p<16,l<4 from grid[b,32,8,8] (bn2 view)
    const float* s2;  // [b,64,32]
    DEV float operator()(int b, int a, int p, int l) const {
        int r = (p << 2) + l;          // c = a; strides 32,16,4,1
        int hb = r >> 5; r &= 31;
        int wb = r >> 4; r &= 15;
        int h = (hb << 2) + (r >> 2);
        int w = (wb << 2) + (r & 3);
        int f3 = (a << 6) + (h << 3) + w;           // grid flat c*64+h*8+w
        return s2[((b << 6) + (f3 >> 5)) * 32 + (f3 & 31)];
    }
};
struct GC3 {     // cx3[b,a,p,l], a<4,p<16,l<32, window 2
    const float* s2;
    DEV float operator()(int b, int a, int p, int l) const {
        int flat = (a << 9) + (p << 5) + l;
        int c = flat >> 6; int r = flat & 63;       // strides 64,16,4,2,1
        int hb = r >> 4; r &= 15;
        int wb = r >> 2; r &= 3;
        int h = (hb << 1) + (r >> 1);
        int w = (wb << 1) + (r & 1);
        int f3 = (c << 6) + (h << 3) + w;
        return s2[((b << 6) + (f3 >> 5)) * 32 + (f3 & 31)];
    }
};
struct GFin {    // xf[b,c,0,l] = y3bn[b,l,c], c<32,l<16
    const float* s3;  // [b,16,32]
    DEV float operator()(int b, int a, int /*p*/, int l) const {
        return s3[(((b << 4) + l) << 5) + a];
    }
};

// ---------------- generic per-patch MPS (fused phi->GEMM->scan->label) ----------------
// cores: [P,L,F,16,16], label: [P,16,O,16], 256 threads/CTA.
// Thread t owns output column c=t of M[b, i*16+j]; acc over F in registers.
template <int Ln, int Fn, int NB, int On, typename G>
DEV void mps_patch(int p, int b0, const G& gth,
                   const float* __restrict__ cores,
                   const float* __restrict__ label,
                   float* __restrict__ out, int osb, int osp, int ooff)
{
    constexpr int Cn = Fn / 2;
    extern __shared__ float sm[];
    float* regA = sm;               // NB*256 floats: phi (f-major) then M, reused
    float* vS   = sm + NB * 256;    // NB*16
    const int tid = threadIdx.x;
    const int c = tid;

    for (int i = tid; i < NB * 16; i += 256) vS[i] = 0.25f;  // LB = D^-1/2

    float acc[NB];

    for (int l = 0; l < Ln; ++l) {
        __syncthreads();
        // phi: [x, 1-x], layout phi[f*NB + b]
        for (int idx = tid; idx < Cn * NB; idx += 256) {
            int f = idx / NB, b = idx % NB;
            float v = gth(b0 + b, f, p, l);
            regA[f * NB + b] = v;
            regA[(f + Cn) * NB + b] = 1.0f - v;
        }
        __syncthreads();
        const float* W = cores + (long)(p * Ln + l) * (Fn * 256);
#pragma unroll
        for (int b = 0; b < NB; ++b) acc[b] = 0.0f;
#pragma unroll 2
        for (int f = 0; f < Fn; f += 4) {
            float w0 = W[(f + 0) * 256 + c];
            float w1 = W[(f + 1) * 256 + c];
            float w2 = W[(f + 2) * 256 + c];
            float w3 = W[(f + 3) * 256 + c];
#pragma unroll
            for (int q = 0; q < NB; q += 4) {
                float4 p0 = *(const float4*)&regA[(f + 0) * NB + q];
                float4 p1 = *(const float4*)&regA[(f + 1) * NB + q];
                float4 p2 = *(const float4*)&regA[(f + 2) * NB + q];
                float4 p3 = *(const float4*)&regA[(f + 3) * NB + q];
                acc[q + 0] = fmaf(p0.x, w0, fmaf(p1.x, w1, fmaf(p2.x, w2, fmaf(p3.x, w3, acc[q + 0]))));
                acc[q + 1] = fmaf(p0.y, w0, fmaf(p1.y, w1, fmaf(p2.y, w2, fmaf(p3.y, w3, acc[q + 1]))));
                acc[q + 2] = fmaf(p0.z, w0, fmaf(p1.z, w1, fmaf(p2.z, w2, fmaf(p3.z, w3, acc[q + 2]))));
                acc[q + 3] = fmaf(p0.w, w0, fmaf(p1.w, w1, fmaf(p2.w, w2, fmaf(p3.w, w3, acc[q + 3]))));
            }
        }
        __syncthreads();  // phi reads done before M overwrites regA
#pragma unroll
        for (int b = 0; b < NB; ++b) regA[b * 256 + c] = acc[b];
        __syncthreads();
        // scan step: v_new[b,j] = sum_i v[b,i] * M[b, i*16+j]
        constexpr int OUTS = NB * 16;
        constexpr int KV = (OUTS + 255) / 256;
        float vnew[KV];
#pragma unroll
        for (int k = 0; k < KV; ++k) {
            int idx = tid + k * 256;
            if (idx < OUTS) {
                int b = idx >> 4, j = idx & 15;
                float s = 0.0f;
#pragma unroll
                for (int i = 0; i < 16; ++i)
                    s = fmaf(vS[b * 16 + i], regA[b * 256 + i * 16 + j], s);
                vnew[k] = s;
            }
        }
        __syncthreads();
#pragma unroll
        for (int k = 0; k < KV; ++k) {
            int idx = tid + k * 256;
            if (idx < OUTS) vS[idx] = vnew[k];
        }
    }
    __syncthreads();
    // Lsum[i,o] = sum_j label[p,i,o,j]  (RB folded in as 0.25 at the end)
    const float* Lp = label + (long)p * (16 * On * 16);
    for (int idx = tid; idx < 16 * On; idx += 256) {
        const float* lp = Lp + idx * 16;
        float s = 0.0f;
#pragma unroll
        for (int j = 0; j < 16; ++j) s += lp[j];
        regA[idx] = s;
    }
    __syncthreads();
    for (int idx = tid; idx < NB * On; idx += 256) {
        int b = idx / On, o = idx - b * On;
        float s = 0.0f;
#pragma unroll
        for (int i = 0; i < 16; ++i)
            s = fmaf(vS[b * 16 + i], regA[i * On + o], s);
        out[(long)(b0 + b) * osb + (long)p * osp + ooff + o] = 0.25f * s;
    }
}

// ---------------- BatchNorm (training batch stats, in place) ----------------
template <int C, int Lc>
DEV void bn_channel(float* data, const float* g, const float* bet)
{
    constexpr int N = 32 * Lc;      // 512 or 1024
    constexpr int NV = N / 256;
    __shared__ float red[66];
    int ch = blockIdx.x, tid = threadIdx.x;
    float vals[NV];
    float s = 0.0f, s2 = 0.0f;
#pragma unroll
    for (int k = 0; k < NV; ++k) {
        int idx = tid + (k << 8);
        int b = idx / Lc, o = idx % Lc;
        float v = data[(b * C + ch) * Lc + o];
        vals[k] = v; s += v; s2 = fmaf(v, v, s2);
    }
#pragma unroll
    for (int off = 16; off; off >>= 1) {
        s  += __shfl_down_sync(0xffffffffu, s,  off);
        s2 += __shfl_down_sync(0xffffffffu, s2, off);
    }
    int w = tid >> 5, lane = tid & 31;
    if (lane == 0) { red[w] = s; red[33 + w] = s2; }
    __syncthreads();
    if (tid < 32) {
        s  = (lane < 8) ? red[lane] : 0.0f;
        s2 = (lane < 8) ? red[33 + lane] : 0.0f;
#pragma unroll
        for (int off = 4; off; off >>= 1) {
            s  += __shfl_down_sync(0xffffffffu, s,  off);
            s2 += __shfl_down_sync(0xffffffffu, s2, off);
        }
        if (lane == 0) { red[0] = s; red[1] = s2; }
    }
    __syncthreads();
    constexpr float inv = 1.0f / (float)N;
    float mu  = red[0] * inv;
    float var = red[1] * inv - mu * mu;
    float sc = rsqrtf(var + 1e-5f) * g[ch];
    float sh = bet[ch] - mu * sc;
#pragma unroll
    for (int k = 0; k < NV; ++k) {
        int idx = tid + (k << 8);
        int b = idx / Lc, o = idx % Lc;
        data[(b * C + ch) * Lc + o] = fmaf(vals[k], sc, sh);
    }
}

// ---------------- kernels ----------------
__global__ void __launch_bounds__(256)
stage1_kernel(const float* x, const float* l1c, const float* l1l,
              const float* c1c, const float* c1l)
{
    if (blockIdx.x < 256)
        mps_patch<4, 96, 32, 16>(blockIdx.x, 0, GLote1{x}, l1c, l1l, g_s1l, 4096, 16, 0);
    else
        mps_patch<3, 32, 32, 16>(blockIdx.x - 256, 0, GConv1{x}, c1c, c1l, g_s1c, 16384, 16, 0);
}

__global__ void __launch_bounds__(256)
bn_s1l_kernel(const float* g, const float* b) { bn_channel<256, 16>(g_s1l, g, b); }
__global__ void __launch_bounds__(256)
bn_s1c_kernel(const float* g, const float* b) { bn_channel<1024, 16>(g_s1c, g, b); }
__global__ void __launch_bounds__(256)
bn_s2_kernel(const float* g, const float* b) { bn_channel<64, 32>(g_s2, g, b); }
__global__ void __launch_bounds__(256)
bn_s3_kernel(const float* g, const float* b) { bn_channel<16, 32>(g_s3, g, b); }

__global__ void __launch_bounds__(256)
stage2_kernel(const float* l2c, const float* l2l, const float* c2c, const float* c2l)
{
    int bi = blockIdx.x;
    if (bi < 128)
        mps_patch<20, 32, 16, 16>(bi >> 1, (bi & 1) << 4, GComb{g_s1l, g_s1c},
                                  l2c, l2l, g_s2, 2048, 32, 0);
    else {
        bi -= 128;
        mps_patch<16, 40, 16, 16>(bi >> 1, (bi & 1) << 4, GConv2{{g_s1l, g_s1c}},
                                  c2c, c2l, g_s2, 2048, 32, 16);
    }
}

__global__ void __launch_bounds__(256)
stage3_kernel(const float* l3c, const float* l3l, const float* c3c, const float* c3l)
{
    int bi = blockIdx.x;
    if (bi < 64)
        mps_patch<4, 64, 8, 16>(bi >> 2, (bi & 3) << 3, GL3{g_s2},
                                l3c, l3l, g_s3, 512, 32, 0);
    else {
        bi -= 64;
        mps_patch<32, 8, 8, 16>(bi >> 2, (bi & 3) << 3, GC3{g_s2},
                                c3c, c3l, g_s3, 512, 32, 16);
    }
}

__global__ void __launch_bounds__(256)
final_kernel(const float* fc, const float* fl, float* outp)
{
    mps_patch<16, 64, 8, 10>(0, blockIdx.x << 3, GFin{g_s3}, fc, fl, outp, 10, 0, 0);
}

// ---------------- launch ----------------
extern "C" void kernel_launch(void* const* d_in, const int* in_sizes, int n_in,
                              void* d_out, int out_size)
{
    const float* x   = (const float*)d_in[0];
    const float* l1c = (const float*)d_in[1];
    const float* l1l = (const float*)d_in[2];
    const float* c1c = (const float*)d_in[3];
    const float* c1l = (const float*)d_in[4];
    const float* l2c = (const float*)d_in[5];
    const float* l2l = (const float*)d_in[6];
    const float* c2c = (const float*)d_in[7];
    const float* c2l = (const float*)d_in[8];
    const float* l3c = (const float*)d_in[9];
    const float* l3l = (const float*)d_in[10];
    const float* c3c = (const float*)d_in[11];
    const float* c3l = (const float*)d_in[12];
    const float* fc  = (const float*)d_in[13];
    const float* fl  = (const float*)d_in[14];
    const float* g1  = (const float*)d_in[15];
    const float* b1  = (const float*)d_in[16];
    const float* gc1 = (const float*)d_in[17];
    const float* bc1 = (const float*)d_in[18];
    const float* g2  = (const float*)d_in[19];
    const float* b2  = (const float*)d_in[20];
    const float* g3  = (const float*)d_in[21];
    const float* b3  = (const float*)d_in[22];
    float* outp = (float*)d_out;

    stage1_kernel<<<1280, 256, (32 * 256 + 32 * 16) * 4>>>(x, l1c, l1l, c1c, c1l);
    bn_s1l_kernel<<<256, 256>>>(g1, b1);
    bn_s1c_kernel<<<1024, 256>>>(gc1, bc1);
    stage2_kernel<<<256, 256, (16 * 256 + 16 * 16) * 4>>>(l2c, l2l, c2c, c2l);
    bn_s2_kernel<<<64, 256>>>(g2, b2);
    stage3_kernel<<<128, 256, (8 * 256 + 8 * 16) * 4>>>(l3c, l3l, c3c, c3l);
    bn_s3_kernel<<<16, 256>>>(g3, b3);
    final_kernel<<<4, 256, (8 * 256 + 8 * 16) * 4>>>(fc, fl, outp);
}